// round 2
// baseline (speedup 1.0000x reference)
#include <cuda_runtime.h>
#include <cuda_bf16.h>
#include <cstdint>

// AddRadiusEdgeIndex: N=8192 points in [0,10]^3, r=1.
// out[0 : N*N)        = masked_dist2 (float32)
// out[N*N : 2*N*N)    = edge_mask as 0.0/1.0 float32
//
// dist2 computed EXACTLY as the reference formula:
//   sq = x*x (+fma y) (+fma z)
//   dot = x_i*x_j (+fma y) (+fma z)
//   dist2 = (sq_i + sq_j) - 2*dot    (explicit rn ops, no re-contraction)
//   dist2 = max(dist2, 0); mask = dist2 <= 1

#define NPTS 8192

__device__ float4 g_pts[NPTS];  // {x, y, z, |p|^2}

__global__ void pack_kernel(const float* __restrict__ pos) {
    int i = blockIdx.x * blockDim.x + threadIdx.x;
    if (i < NPTS) {
        float x = pos[3 * i + 0];
        float y = pos[3 * i + 1];
        float z = pos[3 * i + 2];
        float s = __fmul_rn(x, x);
        s = __fmaf_rn(y, y, s);
        s = __fmaf_rn(z, z, s);
        g_pts[i] = make_float4(x, y, z, s);
    }
}

// Each thread: one row i, 4 consecutive columns j. Two STG.128 per thread.
// grid = (N/(4*blockDim.x), N)
__global__ void __launch_bounds__(256) radius_kernel(float* __restrict__ out) {
    const int i  = blockIdx.y;
    const int j0 = (blockIdx.x * blockDim.x + threadIdx.x) * 4;

    const float4 pi = g_pts[i];

    float d[4], m[4];
#pragma unroll
    for (int k = 0; k < 4; k++) {
        const float4 pj = g_pts[j0 + k];
        float dot = __fmul_rn(pi.x, pj.x);
        dot = __fmaf_rn(pi.y, pj.y, dot);
        dot = __fmaf_rn(pi.z, pj.z, dot);
        // (sq_i + sq_j) - 2*dot  -- keep exact rounding order, no fma contraction
        float dd = __fsub_rn(__fadd_rn(pi.w, pj.w), __fmul_rn(2.0f, dot));
        dd = fmaxf(dd, 0.0f);
        const bool e = (dd <= 1.0f);
        d[k] = e ? dd : 0.0f;
        m[k] = e ? 1.0f : 0.0f;
    }

    const size_t base = (size_t)i * NPTS + (size_t)j0;
    float4* out_d = reinterpret_cast<float4*>(out + base);
    float4* out_m = reinterpret_cast<float4*>(out + (size_t)NPTS * NPTS + base);
    *out_d = make_float4(d[0], d[1], d[2], d[3]);
    *out_m = make_float4(m[0], m[1], m[2], m[3]);
}

extern "C" void kernel_launch(void* const* d_in, const int* in_sizes, int n_in,
                              void* d_out, int out_size) {
    const float* pos = (const float*)d_in[0];
    float* out = (float*)d_out;

    pack_kernel<<<(NPTS + 255) / 256, 256>>>(pos);

    // 256 threads * 4 j per thread = 1024 columns per block -> 8 blocks in x
    dim3 grid(NPTS / (256 * 4), NPTS);
    radius_kernel<<<grid, 256>>>(out);
}

// round 3
// speedup vs baseline: 1.7792x; 1.7792x over previous
#include <cuda_runtime.h>
#include <cuda_bf16.h>
#include <cstdint>

// AddRadiusEdgeIndex: N=8192 points in [0,10]^3, r=1.
// out[0 : N*N)     = masked_dist2 (float32)
// out[N*N : 2*N*N) = edge_mask as 0.0/1.0 float32
//
// dist2 computed EXACTLY as the reference formula (rn ops, no re-contraction).
//
// Tiled: block = 64 rows x 1024 cols. pj in registers (loaded once),
// pi broadcast from smem. Stores = 2x STG.128 per thread per row (streaming).

#define NPTS  8192
#define ITILE 64
#define JTILE 1024   // 256 threads * 4 cols

__device__ float4 g_pts[NPTS];  // {x, y, z, |p|^2}

__global__ void pack_kernel(const float* __restrict__ pos) {
    int i = blockIdx.x * blockDim.x + threadIdx.x;
    if (i < NPTS) {
        float x = pos[3 * i + 0];
        float y = pos[3 * i + 1];
        float z = pos[3 * i + 2];
        float s = __fmul_rn(x, x);
        s = __fmaf_rn(y, y, s);
        s = __fmaf_rn(z, z, s);
        g_pts[i] = make_float4(x, y, z, s);
    }
}

__global__ void __launch_bounds__(256) radius_kernel(float* __restrict__ out) {
    __shared__ float4 s_pi[ITILE];

    const int i0 = blockIdx.y * ITILE;
    const int j0 = blockIdx.x * JTILE + threadIdx.x * 4;

    // Load this thread's 4 column points once; reused for all 64 rows.
    float4 pj[4];
#pragma unroll
    for (int k = 0; k < 4; k++) pj[k] = g_pts[j0 + k];

    // Row tile into smem (threads 0..63, coalesced LDG.128).
    if (threadIdx.x < ITILE) s_pi[threadIdx.x] = g_pts[i0 + threadIdx.x];
    __syncthreads();

    float* od = out + (size_t)i0 * NPTS + j0;
    float* om = od + (size_t)NPTS * NPTS;

#pragma unroll 4
    for (int r = 0; r < ITILE; r++) {
        const float4 pi = s_pi[r];  // broadcast LDS, conflict-free

        float d[4], m[4];
#pragma unroll
        for (int k = 0; k < 4; k++) {
            float dot = __fmul_rn(pi.x, pj[k].x);
            dot = __fmaf_rn(pi.y, pj[k].y, dot);
            dot = __fmaf_rn(pi.z, pj[k].z, dot);
            // (sq_i + sq_j) - 2*dot : exact rounding order, no fma contraction
            float dd = __fsub_rn(__fadd_rn(pi.w, pj[k].w), __fmul_rn(2.0f, dot));
            dd = fmaxf(dd, 0.0f);
            const bool e = (dd <= 1.0f);
            d[k] = e ? dd : 0.0f;
            m[k] = e ? 1.0f : 0.0f;
        }

        __stcs(reinterpret_cast<float4*>(od), make_float4(d[0], d[1], d[2], d[3]));
        __stcs(reinterpret_cast<float4*>(om), make_float4(m[0], m[1], m[2], m[3]));
        od += NPTS;
        om += NPTS;
    }
}

extern "C" void kernel_launch(void* const* d_in, const int* in_sizes, int n_in,
                              void* d_out, int out_size) {
    const float* pos = (const float*)d_in[0];
    float* out = (float*)d_out;

    pack_kernel<<<(NPTS + 255) / 256, 256>>>(pos);

    dim3 grid(NPTS / JTILE, NPTS / ITILE);  // (8, 128)
    radius_kernel<<<grid, 256>>>(out);
}

// round 4
// speedup vs baseline: 1.8592x; 1.0449x over previous
#include <cuda_runtime.h>
#include <cuda_bf16.h>
#include <cstdint>

// AddRadiusEdgeIndex: N=8192 points in [0,10]^3, r=1.
// out[0 : N*N)     = masked_dist2 (float32)
// out[N*N : 2*N*N) = edge_mask as 0.0/1.0 float32
//
// Single fused kernel: block = 64 rows x 1024 cols tile.
// Each block loads its points directly from pos (L2-resident, ~13KB/block),
// computes |p|^2 with the exact reference fma chain, dist2 with exact rn ops.
// Stores: 2x STG.128 streaming per thread per row (536 MB total -> HBM-bound).

#define NPTS  8192
#define ITILE 64
#define JTILE 1024   // 256 threads * 4 cols

__global__ void __launch_bounds__(256) radius_kernel(const float* __restrict__ pos,
                                                     float* __restrict__ out) {
    __shared__ float4 s_pi[ITILE];

    const int i0 = blockIdx.y * ITILE;
    const int j0 = blockIdx.x * JTILE + threadIdx.x * 4;

    // Load this thread's 4 column points from pos; compute sq (exact fma chain).
    float4 pj[4];
#pragma unroll
    for (int k = 0; k < 4; k++) {
        const float x = pos[3 * (j0 + k) + 0];
        const float y = pos[3 * (j0 + k) + 1];
        const float z = pos[3 * (j0 + k) + 2];
        float s = __fmul_rn(x, x);
        s = __fmaf_rn(y, y, s);
        s = __fmaf_rn(z, z, s);
        pj[k] = make_float4(x, y, z, s);
    }

    // Row tile into smem: threads 0..63 each build one pi.
    if (threadIdx.x < ITILE) {
        const int i = i0 + threadIdx.x;
        const float x = pos[3 * i + 0];
        const float y = pos[3 * i + 1];
        const float z = pos[3 * i + 2];
        float s = __fmul_rn(x, x);
        s = __fmaf_rn(y, y, s);
        s = __fmaf_rn(z, z, s);
        s_pi[threadIdx.x] = make_float4(x, y, z, s);
    }
    __syncthreads();

    float* od = out + (size_t)i0 * NPTS + j0;
    float* om = od + (size_t)NPTS * NPTS;

#pragma unroll 4
    for (int r = 0; r < ITILE; r++) {
        const float4 pi = s_pi[r];  // broadcast LDS, conflict-free

        float d[4], m[4];
#pragma unroll
        for (int k = 0; k < 4; k++) {
            float dot = __fmul_rn(pi.x, pj[k].x);
            dot = __fmaf_rn(pi.y, pj[k].y, dot);
            dot = __fmaf_rn(pi.z, pj[k].z, dot);
            // (sq_i + sq_j) - 2*dot : exact rounding order, no fma contraction
            float dd = __fsub_rn(__fadd_rn(pi.w, pj[k].w), __fmul_rn(2.0f, dot));
            dd = fmaxf(dd, 0.0f);
            const bool e = (dd <= 1.0f);
            d[k] = e ? dd : 0.0f;
            m[k] = e ? 1.0f : 0.0f;
        }

        __stcs(reinterpret_cast<float4*>(od), make_float4(d[0], d[1], d[2], d[3]));
        __stcs(reinterpret_cast<float4*>(om), make_float4(m[0], m[1], m[2], m[3]));
        od += NPTS;
        om += NPTS;
    }
}

extern "C" void kernel_launch(void* const* d_in, const int* in_sizes, int n_in,
                              void* d_out, int out_size) {
    const float* pos = (const float*)d_in[0];
    float* out = (float*)d_out;

    dim3 grid(NPTS / JTILE, NPTS / ITILE);  // (8, 128)
    radius_kernel<<<grid, 256>>>(pos, out);
}